// round 14
// baseline (speedup 1.0000x reference)
#include <cuda_runtime.h>
#include <mma.h>
#include <cuda_fp16.h>
#include <math.h>
#include <stdint.h>

using namespace nvcuda;

#define B_   2
#define T_   2048
#define D_   1024
#define H_   8
#define DK   64
#define DV   64
#define R_   64
#define DFF  4096
#define BT   (B_*T_)       // 4096
#define HD   (H_*DK)       // 512
#define NCAT 584           // 512 (drive) + 64 (au) + 8 (beta)
#define NPAD 640           // NCAT padded to 128 multiple

// ---------------- scratch (device globals; no allocation allowed) ----------------
__device__ __align__(256) float g_inv  [BT];
__device__ __align__(256) float g_h    [BT*D_];
__device__ __align__(256) float g_q    [BT*HD];
__device__ __align__(256) float g_k    [BT*HD];
__device__ __align__(256) float g_v    [BT*HD];
__device__ __align__(256) float g_drive[BT*HD];
__device__ __align__(256) float g_ab   [BT*HD];
__device__ __align__(256) float g_au   [BT*R_];
__device__ __align__(256) float g_beta [BT*H_];
__device__ __align__(256) float g_yattn[BT*HD];
__device__ __align__(256) float g_u1   [BT*R_];
__device__ __align__(256) float g_gate [BT*D_];
__device__ __align__(256) float g_y2   [BT*D_];
__device__ __align__(256) float g_wcat [D_*NPAD];
__device__ __align__(256) float g_bcat [NPAD];
// fp16 buffers
__device__ __align__(256) __half g_hh    [BT*D_];
__device__ __align__(256) __half g_yattnh[BT*HD];
__device__ __align__(256) __half g_zh    [BT*D_];
__device__ __align__(256) __half g_ffah  [BT*DFF];
__device__ __align__(256) __half g_wqh   [D_*HD];
__device__ __align__(256) __half g_wkh   [D_*HD];
__device__ __align__(256) __half g_wvh   [D_*HD];
__device__ __align__(256) __half g_woh   [HD*D_];
__device__ __align__(256) __half g_wff1h [D_*DFF];
__device__ __align__(256) __half g_wff3h [D_*DFF];
__device__ __align__(256) __half g_wff2h [DFF*D_];

// ---------------- cp.async helpers ----------------
__device__ __forceinline__ void cp_async16(uint32_t dst, const void* src) {
    asm volatile("cp.async.cg.shared.global [%0], [%1], 16;\n" :: "r"(dst), "l"(src));
}
__device__ __forceinline__ void cp_commit() { asm volatile("cp.async.commit_group;\n" ::: "memory"); }
__device__ __forceinline__ void cp_wait1() { asm volatile("cp.async.wait_group 1;\n" ::: "memory"); }
__device__ __forceinline__ void cp_wait0() { asm volatile("cp.async.wait_group 0;\n" ::: "memory"); }

// ---------------- packed f32x2 helpers ----------------
struct f32x2 { unsigned long long v; };
__device__ __forceinline__ f32x2 f2_zero() { f32x2 r; r.v = 0ull; return r; }
__device__ __forceinline__ f32x2 f2_bcast(float x) {
    f32x2 r; asm("mov.b64 %0, {%1, %1};" : "=l"(r.v) : "f"(x)); return r;
}
__device__ __forceinline__ f32x2 f2_mul(f32x2 a, f32x2 b) {
    f32x2 r; asm("mul.rn.f32x2 %0, %1, %2;" : "=l"(r.v) : "l"(a.v), "l"(b.v)); return r;
}
__device__ __forceinline__ f32x2 f2_add(f32x2 a, f32x2 b) {
    f32x2 r; asm("add.rn.f32x2 %0, %1, %2;" : "=l"(r.v) : "l"(a.v), "l"(b.v)); return r;
}
__device__ __forceinline__ f32x2 f2_fma(f32x2 a, f32x2 b, f32x2 c) {
    f32x2 r; asm("fma.rn.f32x2 %0, %1, %2, %3;" : "=l"(r.v) : "l"(a.v), "l"(b.v), "l"(c.v)); return r;
}
__device__ __forceinline__ float f2_hadd(f32x2 a) {
    float x, y; asm("mov.b64 {%0, %1}, %2;" : "=f"(x), "=f"(y) : "l"(a.v)); return x + y;
}

// ---------------- elementwise / norm / convert kernels ----------------

__global__ void f2h_kernel(const float* __restrict__ in, __half* __restrict__ out, int n4) {
    int i = blockIdx.x * blockDim.x + threadIdx.x;
    if (i >= n4) return;
    float4 v = reinterpret_cast<const float4*>(in)[i];
    __half2* o = reinterpret_cast<__half2*>(out);
    o[2 * i]     = __floats2half2_rn(v.x, v.y);
    o[2 * i + 1] = __floats2half2_rn(v.z, v.w);
}

// concat Wspike|Wau|Wbeta into [D, NPAD] (zero-padded) + bias concat
__global__ void wcat_kernel(const float* __restrict__ Ws, const float* __restrict__ Wa,
                            const float* __restrict__ Wb, const float* __restrict__ bau,
                            const float* __restrict__ bb,
                            float* __restrict__ wcat, float* __restrict__ bcat) {
    int idx = blockIdx.x * blockDim.x + threadIdx.x;
    if (idx < NPAD)
        bcat[idx] = (idx < 512) ? 0.f : (idx < 576) ? bau[idx - 512]
                  : (idx < NCAT) ? bb[idx - 576] : 0.f;
    if (idx >= D_ * NPAD) return;
    int k = idx / NPAD, j = idx % NPAD;
    float v;
    if (j < 512) v = Ws[k * 512 + j];
    else if (j < 576) v = Wa[k * 64 + (j - 512)];
    else if (j < NCAT) v = Wb[k * 8 + (j - 576)];
    else v = 0.f;
    wcat[idx] = v;
}

// per-row rms inverse norm of x
__global__ void rowinv_kernel(const float* __restrict__ x, float* __restrict__ inv) {
    int row = blockIdx.x;
    const float* xr = x + (size_t)row * D_;
    float ss = 0.f;
    for (int i = threadIdx.x; i < D_; i += 256) { float v = xr[i]; ss += v * v; }
    #pragma unroll
    for (int o = 16; o; o >>= 1) ss += __shfl_down_sync(0xffffffffu, ss, o);
    __shared__ float sh[8];
    int lane = threadIdx.x & 31, warp = threadIdx.x >> 5;
    if (lane == 0) sh[warp] = ss;
    __syncthreads();
    if (warp == 0) {
        ss = (lane < 8) ? sh[lane] : 0.f;
        #pragma unroll
        for (int o = 4; o; o >>= 1) ss += __shfl_down_sync(0xffffffffu, ss, o);
        if (lane == 0) sh[0] = ss;
    }
    __syncthreads();
    if (threadIdx.x == 0)
        inv[row] = rsqrtf(sh[0] * (1.f / D_) + 1e-6f);
}

__global__ void rmsnorm_h_kernel(const float* __restrict__ x, const float* __restrict__ w,
                                 __half* __restrict__ out) {
    int row = blockIdx.x;
    const float* xr = x + (size_t)row * D_;
    float ss = 0.f;
    for (int i = threadIdx.x; i < D_; i += 256) { float v = xr[i]; ss += v * v; }
    #pragma unroll
    for (int o = 16; o; o >>= 1) ss += __shfl_down_sync(0xffffffffu, ss, o);
    __shared__ float sh[8];
    int lane = threadIdx.x & 31, warp = threadIdx.x >> 5;
    if (lane == 0) sh[warp] = ss;
    __syncthreads();
    if (warp == 0) {
        ss = (lane < 8) ? sh[lane] : 0.f;
        #pragma unroll
        for (int o = 4; o; o >>= 1) ss += __shfl_down_sync(0xffffffffu, ss, o);
        if (lane == 0) sh[0] = ss;
    }
    __syncthreads();
    float inv = rsqrtf(sh[0] * (1.f / D_) + 1e-6f);
    for (int i = threadIdx.x; i < D_; i += 256)
        out[(size_t)row * D_ + i] = __float2half(xr[i] * inv * w[i]);
}

// fused: hin(bt,d) = (x*inv)*nw, then causal depthwise conv + bias + silu
__global__ void conv_silu_kernel(const float* __restrict__ x, const float* __restrict__ inv,
                                 const float* __restrict__ nw,
                                 const float* __restrict__ w, const float* __restrict__ b,
                                 float* __restrict__ out, __half* __restrict__ outh) {
    int idx = blockIdx.x * blockDim.x + threadIdx.x;
    if (idx >= BT * D_) return;
    int d = idx % D_;
    int bt = idx / D_;
    int t = bt % T_;
    float wn = nw[d];
    float acc = b[d];
    #pragma unroll
    for (int j = 0; j < 4; j++) {
        int tt = t - 3 + j;
        if (tt >= 0) {
            int btj = bt - 3 + j;
            float hv = (x[(size_t)btj * D_ + d] * inv[btj]) * wn;
            acc += hv * w[d * 4 + j];
        }
    }
    float o = acc / (1.f + __expf(-acc));
    out[idx] = o;
    outh[idx] = __float2half(o);
}

__global__ void l2norm2_kernel(float* __restrict__ pq, float* __restrict__ pk) {
    float* p = blockIdx.y ? pk : pq;
    size_t base = (size_t)blockIdx.x * 64;
    float v = p[base + threadIdx.x];
    float ss = v * v;
    #pragma unroll
    for (int o = 16; o; o >>= 1) ss += __shfl_down_sync(0xffffffffu, ss, o);
    __shared__ float sh[2];
    if ((threadIdx.x & 31) == 0) sh[threadIdx.x >> 5] = ss;
    __syncthreads();
    float tot = sh[0] + sh[1];
    p[base + threadIdx.x] = v / (sqrtf(tot) + 1e-6f);
}

__global__ void headnorm_h_kernel(const float* __restrict__ p, const float* __restrict__ w,
                                  __half* __restrict__ out) {
    int h = blockIdx.x % H_;
    size_t base = (size_t)blockIdx.x * 64;
    float v = p[base + threadIdx.x];
    float ss = v * v;
    #pragma unroll
    for (int o = 16; o; o >>= 1) ss += __shfl_down_sync(0xffffffffu, ss, o);
    __shared__ float sh[2];
    if ((threadIdx.x & 31) == 0) sh[threadIdx.x >> 5] = ss;
    __syncthreads();
    float mean = (sh[0] + sh[1]) * (1.f / 64.f);
    out[base + threadIdx.x] = __float2half(v * rsqrtf(mean + 1e-6f) * w[h * 64 + threadIdx.x]);
}

// ---------------- fp32 SIMT GEMMs ----------------

enum { EP_NONE = 0, EP_BIAS = 1, EP_BIAS_SILU = 2, EP_BIAS_SIGMOID = 3,
       EP_RESID_GATE = 4, EP_RESID_ADD = 5, EP_CAT = 6 };

// legacy 64x64 tile (kept for small-N u1 GEMM)
__global__ void __launch_bounds__(256)
sgemm_kernel(const float* __restrict__ A, const float* __restrict__ Bm,
             const float* __restrict__ bias, float* __restrict__ C,
             int M, int N, int K, int mode) {
    __shared__ float As[16][68];
    __shared__ float Bs[16][64];
    int tid = threadIdx.x;
    int tx = tid & 15, ty = tid >> 4;
    int row0 = blockIdx.y * 64;
    int col0 = blockIdx.x * 64;

    int aRow = tid >> 2, aCol = (tid & 3) * 4;
    int bRow = tid >> 4, bCol = (tid & 15) * 4;
    const bool fullN = (col0 + 64 <= N);

    float acc[4][4];
    #pragma unroll
    for (int i = 0; i < 4; i++)
        #pragma unroll
        for (int j = 0; j < 4; j++) acc[i][j] = 0.f;

    for (int k0 = 0; k0 < K; k0 += 16) {
        float4 av = *reinterpret_cast<const float4*>(&A[(size_t)(row0 + aRow) * K + k0 + aCol]);
        As[aCol + 0][aRow] = av.x; As[aCol + 1][aRow] = av.y;
        As[aCol + 2][aRow] = av.z; As[aCol + 3][aRow] = av.w;
        if (fullN) {
            *reinterpret_cast<float4*>(&Bs[bRow][bCol]) =
                *reinterpret_cast<const float4*>(&Bm[(size_t)(k0 + bRow) * N + col0 + bCol]);
        } else {
            #pragma unroll
            for (int u = 0; u < 4; u++) {
                int c = col0 + bCol + u;
                Bs[bRow][bCol + u] = (c < N) ? Bm[(size_t)(k0 + bRow) * N + c] : 0.f;
            }
        }
        __syncthreads();
        #pragma unroll
        for (int kk = 0; kk < 16; kk++) {
            float a[4], b[4];
            *reinterpret_cast<float4*>(a) = *reinterpret_cast<const float4*>(&As[kk][ty * 4]);
            *reinterpret_cast<float4*>(b) = *reinterpret_cast<const float4*>(&Bs[kk][tx * 4]);
            #pragma unroll
            for (int i = 0; i < 4; i++)
                #pragma unroll
                for (int j = 0; j < 4; j++) acc[i][j] = fmaf(a[i], b[j], acc[i][j]);
        }
        __syncthreads();
    }

    #pragma unroll
    for (int i = 0; i < 4; i++) {
        int r = row0 + ty * 4 + i;
        #pragma unroll
        for (int j = 0; j < 4; j++) {
            int c = col0 + tx * 4 + j;
            if (c >= N) continue;
            float a = acc[i][j], o;
            if (mode == EP_BIAS) o = a + bias[c];
            else if (mode == EP_BIAS_SILU) { float t = a + bias[c]; o = t / (1.f + __expf(-t)); }
            else o = a;
            C[(size_t)r * N + c] = o;
        }
    }
}

// 128x128 tile, 8x8 microtile (split 4+4). M%128==0, N%128==0, K%16==0.
__global__ void __launch_bounds__(256)
sgemm128_kernel(const float* __restrict__ A, const float* __restrict__ Bm,
                const float* __restrict__ bias, const float* __restrict__ gate,
                float* __restrict__ C,
                float* __restrict__ outAu, float* __restrict__ outBeta,
                int N, int K, int mode) {
    __shared__ float As[16][132];
    __shared__ float Bs[16][132];
    int tid = threadIdx.x;
    int tx = tid & 15, ty = tid >> 4;
    int row0 = blockIdx.y * 128;
    int col0 = blockIdx.x * 128;

    float acc[8][8];
    #pragma unroll
    for (int i = 0; i < 8; i++)
        #pragma unroll
        for (int j = 0; j < 8; j++) acc[i][j] = 0.f;

    for (int k0 = 0; k0 < K; k0 += 16) {
        // load A 128x16 (transpose into As[k][r]) and B 16x128
        #pragma unroll
        for (int l = 0; l < 2; l++) {
            int lin = tid + (l << 8);
            int ar = lin >> 2, ac4 = (lin & 3) << 2;
            float4 av = *reinterpret_cast<const float4*>(&A[(size_t)(row0 + ar) * K + k0 + ac4]);
            As[ac4 + 0][ar] = av.x; As[ac4 + 1][ar] = av.y;
            As[ac4 + 2][ar] = av.z; As[ac4 + 3][ar] = av.w;
            int br = lin >> 5, bc = (lin & 31) << 2;
            *reinterpret_cast<float4*>(&Bs[br][bc]) =
                *reinterpret_cast<const float4*>(&Bm[(size_t)(k0 + br) * N + col0 + bc]);
        }
        __syncthreads();
        #pragma unroll
        for (int kk = 0; kk < 16; kk++) {
            float a[8], b[8];
            *reinterpret_cast<float4*>(a)     = *reinterpret_cast<const float4*>(&As[kk][ty * 4]);
            *reinterpret_cast<float4*>(a + 4) = *reinterpret_cast<const float4*>(&As[kk][64 + ty * 4]);
            *reinterpret_cast<float4*>(b)     = *reinterpret_cast<const float4*>(&Bs[kk][tx * 4]);
            *reinterpret_cast<float4*>(b + 4) = *reinterpret_cast<const float4*>(&Bs[kk][64 + tx * 4]);
            #pragma unroll
            for (int i = 0; i < 8; i++)
                #pragma unroll
                for (int j = 0; j < 8; j++) acc[i][j] = fmaf(a[i], b[j], acc[i][j]);
        }
        __syncthreads();
    }

    #pragma unroll
    for (int i = 0; i < 8; i++) {
        int r = row0 + ((i < 4) ? (ty * 4 + i) : (64 + ty * 4 + i - 4));
        #pragma unroll
        for (int j = 0; j < 8; j++) {
            int c = col0 + ((j < 4) ? (tx * 4 + j) : (64 + tx * 4 + j - 4));
            float a = acc[i][j];
            if (mode == EP_CAT) {
                if (c >= NCAT) continue;
                float t = a + bias[c];
                if (c < 512) C[(size_t)r * 512 + c] = t;                       // drive
                else if (c < 576) outAu[(size_t)r * 64 + (c - 512)] = t / (1.f + __expf(-t));
                else outBeta[(size_t)r * 8 + (c - 576)] = t;                   // beta base
                continue;
            }
            float o;
            if (mode == EP_BIAS) o = a + bias[c];
            else if (mode == EP_BIAS_SIGMOID) { float t = a + bias[c]; o = 1.f / (1.f + __expf(-t)); }
            else o = a;
            C[(size_t)r * N + c] = o;
        }
    }
}

// ---------------- fp16 GEMM: m16n16k16 HMMA, cp.async double-buffered ----------------

#define HLDA 40
#define HLDB 136

__device__ __forceinline__ void hgemm_core(
    const __half* __restrict__ A, const __half* __restrict__ Bm,
    const float* __restrict__ resid, const float* __restrict__ gate,
    float* __restrict__ C, int N, int K, int mode, int row0, int col0,
    __half* sA, __half* sB)
{
    int tid = threadIdx.x;
    int warp = tid >> 5, warpM = warp & 3, warpN = warp >> 2;

    uint32_t sAu = (uint32_t)__cvta_generic_to_shared(sA);
    uint32_t sBu = (uint32_t)__cvta_generic_to_shared(sB);

    wmma::fragment<wmma::accumulator, 16, 16, 16, float> acc[2][4];
    #pragma unroll
    for (int i = 0; i < 2; i++)
        #pragma unroll
        for (int j = 0; j < 4; j++) wmma::fill_fragment(acc[i][j], 0.f);

    auto issue = [&](int stage, int k0) {
        uint32_t oA = (uint32_t)(stage * 128 * HLDA * 2);
        uint32_t oB = (uint32_t)(stage * 32 * HLDB * 2);
        #pragma unroll
        for (int i = 0; i < 2; i++) {
            int c = tid + (i << 8);
            int arr = c >> 2, acc_ = (c & 3) << 3;
            cp_async16(sAu + oA + (uint32_t)(arr * HLDA + acc_) * 2u,
                       A + (size_t)(row0 + arr) * K + k0 + acc_);
            int brr = c >> 4, bcc = (c & 15) << 3;
            cp_async16(sBu + oB + (uint32_t)(brr * HLDB + bcc) * 2u,
                       Bm + (size_t)(k0 + brr) * N + col0 + bcc);
        }
        cp_commit();
    };

    int nk = K >> 5;
    issue(0, 0);
    for (int ks = 0; ks < nk; ks++) {
        int buf = ks & 1;
        if (ks + 1 < nk) { issue(buf ^ 1, (ks + 1) << 5); cp_wait1(); }
        else cp_wait0();
        __syncthreads();
        __half* cA = sA + buf * 128 * HLDA;
        __half* cB = sB + buf * 32 * HLDB;
        #pragma unroll
        for (int kk = 0; kk < 32; kk += 16) {
            wmma::fragment<wmma::matrix_a, 16, 16, 16, __half, wmma::row_major> af[2];
            wmma::fragment<wmma::matrix_b, 16, 16, 16, __half, wmma::row_major> bf[4];
            #pragma unroll
            for (int i = 0; i < 2; i++)
                wmma::load_matrix_sync(af[i], &cA[(warpM * 32 + i * 16) * HLDA + kk], HLDA);
            #pragma unroll
            for (int j = 0; j < 4; j++)
                wmma::load_matrix_sync(bf[j], &cB[kk * HLDB + warpN * 64 + j * 16], HLDB);
            #pragma unroll
            for (int i = 0; i < 2; i++)
                #pragma unroll
                for (int j = 0; j < 4; j++)
                    wmma::mma_sync(acc[i][j], af[i], bf[j], acc[i][j]);
        }
        __syncthreads();
    }

    #pragma unroll
    for (int i = 0; i < 2; i++) {
        #pragma unroll
        for (int j = 0; j < 4; j++) {
            int r = row0 + warpM * 32 + i * 16;
            int c = col0 + warpN * 64 + j * 16;
            if (mode == EP_RESID_ADD) {
                wmma::fragment<wmma::accumulator, 16, 16, 16, float> rf;
                wmma::load_matrix_sync(rf, &resid[(size_t)r * N + c], N, wmma::mem_row_major);
                #pragma unroll
                for (int e = 0; e < rf.num_elements; e++) acc[i][j].x[e] += rf.x[e];
            } else if (mode == EP_RESID_GATE) {
                wmma::fragment<wmma::accumulator, 16, 16, 16, float> rf, gf;
                wmma::load_matrix_sync(rf, &resid[(size_t)r * N + c], N, wmma::mem_row_major);
                wmma::load_matrix_sync(gf, &gate[(size_t)r * N + c], N, wmma::mem_row_major);
                #pragma unroll
                for (int e = 0; e < rf.num_elements; e++)
                    acc[i][j].x[e] = rf.x[e] + acc[i][j].x[e] * gf.x[e];
            }
            wmma::store_matrix_sync(&C[(size_t)r * N + c], acc[i][j], N, wmma::mem_row_major);
        }
    }
}

__global__ void __launch_bounds__(256)
hgemm_kernel(const __half* __restrict__ A, const __half* __restrict__ Bm,
             const float* __restrict__ resid, const float* __restrict__ gate,
             float* __restrict__ C, int N, int K, int mode) {
    __shared__ __half sA[2 * 128 * HLDA];
    __shared__ __half sB[2 * 32 * HLDB];
    hgemm_core(A, Bm, resid, gate, C, N, K, mode, blockIdx.y * 128, blockIdx.x * 128, sA, sB);
}

__global__ void __launch_bounds__(256)
hqkv_kernel(const __half* __restrict__ A,
            const __half* __restrict__ Wq, const __half* __restrict__ Wk,
            const __half* __restrict__ Wv,
            float* __restrict__ Cq, float* __restrict__ Ck, float* __restrict__ Cv,
            int N, int K) {
    __shared__ __half sA[2 * 128 * HLDA];
    __shared__ __half sB[2 * 32 * HLDB];
    const __half* Bm = (blockIdx.z == 0) ? Wq : (blockIdx.z == 1) ? Wk : Wv;
    float* C = (blockIdx.z == 0) ? Cq : (blockIdx.z == 1) ? Ck : Cv;
    hgemm_core(A, Bm, nullptr, nullptr, C, N, K, EP_NONE, blockIdx.y * 128, blockIdx.x * 128, sA, sB);
}

// fp16 dual GEMM with direct fp16 output
#define HLDBD 72

__global__ void __launch_bounds__(256)
hdual_kernel(const __half* __restrict__ A, const __half* __restrict__ B1,
             const __half* __restrict__ B3, __half* __restrict__ C, int N, int K) {
    __shared__ __half sA[2 * 128 * HLDA];
    __shared__ __half sB1[2 * 32 * HLDBD];
    __shared__ __half sB3[2 * 32 * HLDBD];
    int tid = threadIdx.x;
    int lane = tid & 31;
    int warp = tid >> 5, warpM = warp & 3, warpN = warp >> 2;
    int row0 = blockIdx.y * 128;
    int col0 = blockIdx.x * 64;

    uint32_t sAu = (uint32_t)__cvta_generic_to_shared(sA);
    uint32_t sB1u = (uint32_t)__cvta_generic_to_shared(sB1);
    uint32_t sB3u = (uint32_t)__cvta_generic_to_shared(sB3);

    wmma::fragment<wmma::accumulator, 16, 16, 16, float> acc1[2][2], acc3[2][2];
    #pragma unroll
    for (int i = 0; i < 2; i++)
        #pragma unroll
        for (int j = 0; j < 2; j++) { wmma::fill_fragment(acc1[i][j], 0.f); wmma::fill_fragment(acc3[i][j], 0.f); }

    auto issue = [&](int stage, int k0) {
        uint32_t oA = (uint32_t)(stage * 128 * HLDA * 2);
        uint32_t oB = (uint32_t)(stage * 32 * HLDBD * 2);
        #pragma unroll
        for (int i = 0; i < 2; i++) {
            int c = tid + (i << 8);
            int arr = c >> 2, acc_ = (c & 3) << 3;
            cp_async16(sAu + oA + (uint32_t)(arr * HLDA + acc_) * 2u,
                       A + (size_t)(row0 + arr) * K + k0 + acc_);
        }
        int brr = tid >> 3, bcc = (tid & 7) << 3;
        cp_async16(sB1u + oB + (uint32_t)(brr * HLDBD + bcc) * 2u,
                   B1 + (size_t)(k0 + brr) * N + col0 + bcc);
        cp_async16(sB3u + oB + (uint32_t)(brr * HLDBD + bcc) * 2u,
                   B3 + (size_t)(k0 + brr) * N + col0 + bcc);
        cp_commit();
    };

    int nk = K >> 5;
    issue(0, 0);
    for (int ks = 0; ks < nk; ks++) {
        int buf = ks & 1;
        if (ks + 1 < nk) { issue(buf ^ 1, (ks + 1) << 5); cp_wait1(); }
        else cp_wait0();
        __syncthreads();
        __half* cA = sA + buf * 128 * HLDA;
        __half* cB1 = sB1 + buf * 32 * HLDBD;
        __half* cB3 = sB3 + buf * 32 * HLDBD;
        #pragma unroll
        for (int kk = 0; kk < 32; kk += 16) {
            wmma::fragment<wmma::matrix_a, 16, 16, 16, __half, wmma::row_major> af[2];
            wmma::fragment<wmma::matrix_b, 16, 16, 16, __half, wmma::row_major> b1f[2], b3f[2];
            #pragma unroll
            for (int i = 0; i < 2; i++)
                wmma::load_matrix_sync(af[i], &cA[(warpM * 32 + i * 16) * HLDA + kk], HLDA);
            #pragma unroll
            for (int j = 0; j < 2; j++) {
                wmma::load_matrix_sync(b1f[j], &cB1[kk * HLDBD + warpN * 32 + j * 16], HLDBD);
                wmma::load_matrix_sync(b3f[j], &cB3[kk * HLDBD + warpN * 32 + j * 16], HLDBD);
            }
            #pragma unroll
            for (int i = 0; i < 2; i++)
                #pragma unroll
                for (int j = 0; j < 2; j++) {
                    wmma::mma_sync(acc1[i][j], af[i], b1f[j], acc1[i][j]);
                    wmma::mma_sync(acc3[i][j], af[i], b3f[j], acc3[i][j]);
                }
        }
        __syncthreads();
    }
    float* stage = reinterpret_cast<float*>(sA) + warp * 256;
    #pragma unroll
    for (int i = 0; i < 2; i++)
        #pragma unroll
        for (int j = 0; j < 2; j++) {
            #pragma unroll
            for (int e = 0; e < acc1[i][j].num_elements; e++) {
                float t = acc1[i][j].x[e];
                acc1[i][j].x[e] = (t / (1.f + __expf(-t))) * acc3[i][j].x[e];
            }
            wmma::store_matrix_sync(stage, acc1[i][j], 16, wmma::mem_row_major);
            __syncwarp();
            int r = lane >> 1, c0 = (lane & 1) << 3;
            int R = row0 + warpM * 32 + i * 16 + r;
            int Cc = col0 + warpN * 32 + j * 16 + c0;
            __half2* dst = reinterpret_cast<__half2*>(C + (size_t)R * N + Cc);
            #pragma unroll
            for (int u = 0; u < 4; u++)
                dst[u] = __floats2half2_rn(stage[r * 16 + c0 + 2 * u], stage[r * 16 + c0 + 2 * u + 1]);
            __syncwarp();
        }
}

// ---------------- scan: column-per-thread, 4-way split accumulators ----------------
__global__ void __launch_bounds__(64)
scan2_kernel(const float* __restrict__ q, const float* __restrict__ k,
             const float* __restrict__ v, const float* __restrict__ drive,
             const float* __restrict__ ab, const float* __restrict__ betab,
             const float* __restrict__ asp, const float* __restrict__ bsp,
             float* __restrict__ yout) {
    int bh = blockIdx.x;
    int b = bh / H_, h = bh % H_;
    int tid = threadIdx.x;
    int lane = tid & 31, warp = tid >> 5;

    __shared__ __align__(8) float sk[2][64], sq_[2][64], sal[2][64];
    __shared__ float wsum[2][2];

    f32x2 s2[32];
    #pragma unroll
    for (int i = 0; i < 32; i++) s2[i] = f2_zero();

    float m = 0.f;
    float aspv = asp[h * 64 + tid];
    float bspv = bsp[h * 64 + tid];

    size_t rowbase = (size_t)(b * T_) * HD + (size_t)h * 64;
    const float* bb = betab + (size_t)(b * T_) * H_ + h;

    size_t qo = rowbase;
    float dv_ = drive[qo + tid], abv = ab[qo + tid];
    float kv = k[qo + tid], qv = q[qo + tid], vv = v[qo + tid];
    float bbv = bb[0];

    for (int t = 0; t < T_; t++) {
        int pb = t & 1;
        size_t qn = qo + HD;
        m = 0.9f * m + dv_;
        float spk = (m > 0.5f) ? 1.f : 0.f;
        m -= 0.5f * spk;
        float al = 1.f / (1.f + __expf(-(abv + aspv * spk)));
        sk[pb][tid] = kv;
        sq_[pb][tid] = qv;
        sal[pb][tid] = al;
        float sb = spk * bspv;
        #pragma unroll
        for (int o = 16; o; o >>= 1) sb += __shfl_down_sync(0xffffffffu, sb, o);
        if (lane == 0) wsum[pb][warp] = sb;
        float vcur = vv, bbcur = bbv;
        if (t + 1 < T_) {
            dv_ = drive[qn + tid]; abv = ab[qn + tid];
            kv = k[qn + tid]; qv = q[qn + tid]; vv = v[qn + tid];
            bbv = bb[(size_t)(t + 1) * H_];
        }
        int cnt = __syncthreads_count(spk > 0.5f);
        const unsigned long long* k2 = (const unsigned long long*)sk[pb];
        const unsigned long long* q2 = (const unsigned long long*)sq_[pb];
        const unsigned long long* a2 = (const unsigned long long*)sal[pb];
        float out;
        if (cnt > 0) {
            f32x2 p0 = f2_zero(), p1 = f2_zero(), p2 = f2_zero(), p3 = f2_zero();
            f32x2 kr[32];
            #pragma unroll
            for (int i = 0; i < 32; i += 4) {
                kr[i].v = k2[i]; kr[i+1].v = k2[i+1]; kr[i+2].v = k2[i+2]; kr[i+3].v = k2[i+3];
                f32x2 a0, a1, a3, a4;
                a0.v = a2[i]; a1.v = a2[i+1]; a3.v = a2[i+2]; a4.v = a2[i+3];
                s2[i]   = f2_mul(s2[i],   a0);
                s2[i+1] = f2_mul(s2[i+1], a1);
                s2[i+2] = f2_mul(s2[i+2], a3);
                s2[i+3] = f2_mul(s2[i+3], a4);
                p0 = f2_fma(kr[i],   s2[i],   p0);
                p1 = f2_fma(kr[i+1], s2[i+1], p1);
                p2 = f2_fma(kr[i+2], s2[i+2], p2);
                p3 = f2_fma(kr[i+3], s2[i+3], p3);
            }
            float pred = f2_hadd(f2_add(f2_add(p0, p1), f2_add(p2, p3)));
            float braw = bbcur + wsum[pb][0] + wsum[pb][1];
            float beta = 1.f / (1.f + __expf(-braw));
            float bd = beta * (vcur - pred);
            f32x2 bd2 = f2_bcast(bd);
            f32x2 o0 = f2_zero(), o1 = f2_zero(), o2 = f2_zero(), o3 = f2_zero();
            #pragma unroll
            for (int i = 0; i < 32; i += 4) {
                f32x2 q0, q1, q3, q4;
                q0.v = q2[i]; q1.v = q2[i+1]; q3.v = q2[i+2]; q4.v = q2[i+3];
                s2[i]   = f2_fma(kr[i],   bd2, s2[i]);
                s2[i+1] = f2_fma(kr[i+1], bd2, s2[i+1]);
                s2[i+2] = f2_fma(kr[i+2], bd2, s2[i+2]);
                s2[i+3] = f2_fma(kr[i+3], bd2, s2[i+3]);
                o0 = f2_fma(q0, s2[i],   o0);
                o1 = f2_fma(q1, s2[i+1], o1);
                o2 = f2_fma(q3, s2[i+2], o2);
                o3 = f2_fma(q4, s2[i+3], o3);
            }
            out = f2_hadd(f2_add(f2_add(o0, o1), f2_add(o2, o3)));
        } else {
            f32x2 o0 = f2_zero(), o1 = f2_zero(), o2 = f2_zero(), o3 = f2_zero();
            #pragma unroll
            for (int i = 0; i < 32; i += 4) {
                f32x2 q0, q1, q3, q4;
                q0.v = q2[i]; q1.v = q2[i+1]; q3.v = q2[i+2]; q4.v = q2[i+3];
                o0 = f2_fma(q0, s2[i],   o0);
                o1 = f2_fma(q1, s2[i+1], o1);
                o2 = f2_fma(q3, s2[i+2], o2);
                o3 = f2_fma(q4, s2[i+3], o3);
            }
            out = f2_hadd(f2_add(f2_add(o0, o1), f2_add(o2, o3)));
        }
        yout[qo + tid] = out;
        qo = qn;
    }
}

// ---------------- host launch ----------------

template <typename Tsym>
static void* symaddr_v(const Tsym& s) {
    void* p = nullptr;
    cudaGetSymbolAddress(&p, s);
    return p;
}

static void hgemm(const __half* A, const __half* Bm, const float* resid,
                  const float* gate, float* C, int M, int N, int K, int mode) {
    dim3 grid(N / 128, M / 128);
    hgemm_kernel<<<grid, 256>>>(A, Bm, resid, gate, C, N, K, mode);
}

static void f2h_s(cudaStream_t st, const float* in, __half* out, int n) {
    f2h_kernel<<<(n / 4 + 255) / 256, 256, 0, st>>>(in, out, n / 4);
}

extern "C" void kernel_launch(void* const* d_in, const int* in_sizes, int n_in,
                              void* d_out, int out_size) {
    const float* x          = (const float*)d_in[0];
    const float* norm_in_w  = (const float*)d_in[1];
    const float* conv_w     = (const float*)d_in[2];
    const float* conv_b     = (const float*)d_in[3];
    const float* Wq         = (const float*)d_in[4];
    const float* Wk         = (const float*)d_in[5];
    const float* Wv         = (const float*)d_in[6];
    const float* Wo         = (const float*)d_in[7];
    const float* Wspike     = (const float*)d_in[8];
    const float* Wau        = (const float*)d_in[9];
    const float* bau        = (const float*)d_in[10];
    const float* Wad        = (const float*)d_in[11];
    const float* bad        = (const float*)d_in[12];
    const float* alpha_sp   = (const float*)d_in[13];
    const float* Wbeta      = (const float*)d_in[14];
    const float* bbeta      = (const float*)d_in[15];
    const float* beta_sp    = (const float*)d_in[16];
    const float* head_nw    = (const float*)d_in[17];
    const float* Wu1        = (const float*)d_in[18];
    const float* bu1        = (const float*)d_in[19];
    const float* Wu2        = (const float*)d_in[20];
    const float* bu2        = (const float*)d_in[21];
    const float* ff_norm_w  = (const float*)d_in[22];
    const float* Wff1       = (const float*)d_in[23];
    const float* Wff3       = (const float*)d_in[24];
    const float* Wff2       = (const float*)d_in[25];
    float* out = (float*)d_out;

    float* p_inv    = (float*)symaddr_v(g_inv);
    float* p_h      = (float*)symaddr_v(g_h);
    float* p_q      = (float*)symaddr_v(g_q);
    float* p_k      = (float*)symaddr_v(g_k);
    float* p_v      = (float*)symaddr_v(g_v);
    float* p_drive  = (float*)symaddr_v(g_drive);
    float* p_ab     = (float*)symaddr_v(g_ab);
    float* p_au     = (float*)symaddr_v(g_au);
    float* p_beta   = (float*)symaddr_v(g_beta);
    float* p_yattn  = (float*)symaddr_v(g_yattn);
    float* p_u1     = (float*)symaddr_v(g_u1);
    float* p_gate   = (float*)symaddr_v(g_gate);
    float* p_y2     = (float*)symaddr_v(g_y2);
    float* p_wcat   = (float*)symaddr_v(g_wcat);
    float* p_bcat   = (float*)symaddr_v(g_bcat);
    __half* p_hh    = (__half*)symaddr_v(g_hh);
    __half* p_yattnh= (__half*)symaddr_v(g_yattnh);
    __half* p_zh    = (__half*)symaddr_v(g_zh);
    __half* p_ffah  = (__half*)symaddr_v(g_ffah);
    __half* p_wqh   = (__half*)symaddr_v(g_wqh);
    __half* p_wkh   = (__half*)symaddr_v(g_wkh);
    __half* p_wvh   = (__half*)symaddr_v(g_wvh);
    __half* p_woh   = (__half*)symaddr_v(g_woh);
    __half* p_wff1h = (__half*)symaddr_v(g_wff1h);
    __half* p_wff3h = (__half*)symaddr_v(g_wff3h);
    __half* p_wff2h = (__half*)symaddr_v(g_wff2h);

    // one-time host-side resources (no device memory)
    static cudaStream_t s1 = nullptr, s2 = nullptr, s3 = nullptr;
    static cudaEvent_t ev0, ev1, evh, ev2, ev3, ev4;
    if (s1 == nullptr) {
        cudaStreamCreateWithFlags(&s1, cudaStreamNonBlocking);
        cudaStreamCreateWithFlags(&s2, cudaStreamNonBlocking);
        cudaStreamCreateWithFlags(&s3, cudaStreamNonBlocking);
        cudaEventCreateWithFlags(&ev0, cudaEventDisableTiming);
        cudaEventCreateWithFlags(&ev1, cudaEventDisableTiming);
        cudaEventCreateWithFlags(&evh, cudaEventDisableTiming);
        cudaEventCreateWithFlags(&ev2, cudaEventDisableTiming);
        cudaEventCreateWithFlags(&ev3, cudaEventDisableTiming);
        cudaEventCreateWithFlags(&ev4, cudaEventDisableTiming);
    }

    // fork: weight prep on s1, concurrent with rowinv+conv on main
    cudaEventRecord(ev0, 0);
    cudaStreamWaitEvent(s1, ev0, 0);
    f2h_s(s1, Wq, p_wqh, D_ * HD);
    f2h_s(s1, Wk, p_wkh, D_ * HD);
    f2h_s(s1, Wv, p_wvh, D_ * HD);
    f2h_s(s1, Wo, p_woh, HD * D_);
    f2h_s(s1, Wff1, p_wff1h, D_ * DFF);
    f2h_s(s1, Wff3, p_wff3h, D_ * DFF);
    f2h_s(s1, Wff2, p_wff2h, DFF * D_);
    wcat_kernel<<<(D_ * NPAD + 255) / 256, 256, 0, s1>>>(Wspike, Wau, Wbeta, bau, bbeta, p_wcat, p_bcat);
    cudaEventRecord(ev1, s1);

    // main: row inv-norms + fused norm*conv+silu
    rowinv_kernel<<<BT, 256>>>(x, p_inv);
    conv_silu_kernel<<<(BT * D_ + 255) / 256, 256>>>(x, p_inv, norm_in_w, conv_w, conv_b, p_h, p_hh);
    cudaEventRecord(evh, 0);
    cudaStreamWaitEvent(0, ev1, 0);   // main needs fp16 weights for QKV

    // fork: drive/alpha path (fp32, 128x128 SIMT) on s3 — overlaps QKV
    cudaStreamWaitEvent(s3, evh, 0);
    cudaStreamWaitEvent(s3, ev1, 0);
    {
        dim3 grid(NPAD / 128, BT / 128);
        sgemm128_kernel<<<grid, 256, 0, s3>>>(p_h, p_wcat, p_bcat, nullptr, p_drive,
                                              p_au, p_beta, NPAD, D_, EP_CAT);
    }
    {
        dim3 grid(HD / 128, BT / 128);
        sgemm128_kernel<<<grid, 256, 0, s3>>>(p_au, Wad, bad, nullptr, p_ab,
                                              nullptr, nullptr, HD, R_, EP_BIAS);
    }
    cudaEventRecord(ev4, s3);

    // main: q/k/v projections (fp16 HMMA) + l2norm
    {
        dim3 grid(HD / 128, BT / 128, 3);
        hqkv_kernel<<<grid, 256>>>(p_hh, p_wqh, p_wkh, p_wvh, p_q, p_k, p_v, HD, D_);
    }
    {
        dim3 grid(BT * H_, 2);
        l2norm2_kernel<<<grid, 64>>>(p_q, p_k);
    }
    cudaEventRecord(ev2, 0);

    // fork: gate path on s2, scheduled into the scan's idle window
    cudaStreamWaitEvent(s2, ev2, 0);
    {
        dim3 grid(1, BT / 64);
        sgemm_kernel<<<grid, 256, 0, s2>>>(x, Wu1, bu1, p_u1, BT, R_, D_, EP_BIAS_SILU);
    }
    {
        dim3 grid(D_ / 128, BT / 128);
        sgemm128_kernel<<<grid, 256, 0, s2>>>(p_u1, Wu2, bu2, nullptr, p_gate,
                                              nullptr, nullptr, D_, R_, EP_BIAS_SIGMOID);
    }
    cudaEventRecord(ev3, s2);

    // main: join drive path, then scan (gate path fills the idle SMs)
    cudaStreamWaitEvent(0, ev4, 0);
    scan2_kernel<<<B_ * H_, 64>>>(p_q, p_k, p_v, p_drive, p_ab, p_beta,
                                  alpha_sp, beta_sp, p_yattn);
    headnorm_h_kernel<<<BT * H_, 64>>>(p_yattn, head_nw, p_yattnh);
    cudaStreamWaitEvent(0, ev3, 0);   // join: need gate

    // y2 = x + (yattn@Wo) * gate
    hgemm(p_yattnh, p_woh, x, p_gate, p_y2, BT, D_, HD, EP_RESID_GATE);
    // FFN
    rmsnorm_h_kernel<<<BT, 256>>>(p_y2, ff_norm_w, p_zh);
    {
        dim3 grid(DFF / 64, BT / 128);
        hdual_kernel<<<grid, 256>>>(p_zh, p_wff1h, p_wff3h, p_ffah, DFF, D_);
    }
    hgemm(p_ffah, p_wff2h, p_y2, nullptr, out, BT, D_, DFF, EP_RESID_ADD);
}

// round 15
// speedup vs baseline: 1.0237x; 1.0237x over previous
#include <cuda_runtime.h>
#include <mma.h>
#include <cuda_fp16.h>
#include <math.h>
#include <stdint.h>

using namespace nvcuda;

#define B_   2
#define T_   2048
#define D_   1024
#define H_   8
#define DK   64
#define DV   64
#define R_   64
#define DFF  4096
#define BT   (B_*T_)       // 4096
#define HD   (H_*DK)       // 512
#define NCAT 584           // 512 (drive) + 64 (au) + 8 (beta)

// ---------------- scratch (device globals; no allocation allowed) ----------------
__device__ __align__(256) float g_tmp  [BT*D_];
__device__ __align__(256) float g_h    [BT*D_];
__device__ __align__(256) float g_q    [BT*HD];
__device__ __align__(256) float g_k    [BT*HD];
__device__ __align__(256) float g_v    [BT*HD];
__device__ __align__(256) float g_drive[BT*HD];
__device__ __align__(256) float g_ab   [BT*HD];
__device__ __align__(256) float g_au   [BT*R_];
__device__ __align__(256) float g_beta [BT*H_];
__device__ __align__(256) float g_yattn[BT*HD];
__device__ __align__(256) float g_u1   [BT*R_];
__device__ __align__(256) float g_gate [BT*D_];
__device__ __align__(256) float g_y2   [BT*D_];
__device__ __align__(256) float g_wcat [D_*NCAT];
__device__ __align__(256) float g_bcat [NCAT];
// fp16 buffers
__device__ __align__(256) __half g_hh    [BT*D_];
__device__ __align__(256) __half g_yattnh[BT*HD];
__device__ __align__(256) __half g_zh    [BT*D_];
__device__ __align__(256) __half g_ffah  [BT*DFF];
__device__ __align__(256) __half g_wqh   [D_*HD];
__device__ __align__(256) __half g_wkh   [D_*HD];
__device__ __align__(256) __half g_wvh   [D_*HD];
__device__ __align__(256) __half g_woh   [HD*D_];
__device__ __align__(256) __half g_wff1h [D_*DFF];
__device__ __align__(256) __half g_wff3h [D_*DFF];
__device__ __align__(256) __half g_wff2h [DFF*D_];

// ---------------- cp.async helpers ----------------
__device__ __forceinline__ void cp_async16(uint32_t dst, const void* src) {
    asm volatile("cp.async.cg.shared.global [%0], [%1], 16;\n" :: "r"(dst), "l"(src));
}
__device__ __forceinline__ void cp_commit() { asm volatile("cp.async.commit_group;\n" ::: "memory"); }
__device__ __forceinline__ void cp_wait1() { asm volatile("cp.async.wait_group 1;\n" ::: "memory"); }
__device__ __forceinline__ void cp_wait0() { asm volatile("cp.async.wait_group 0;\n" ::: "memory"); }

// ---------------- packed f32x2 helpers ----------------
struct f32x2 { unsigned long long v; };
__device__ __forceinline__ f32x2 f2_zero() { f32x2 r; r.v = 0ull; return r; }
__device__ __forceinline__ f32x2 f2_bcast(float x) {
    f32x2 r; asm("mov.b64 %0, {%1, %1};" : "=l"(r.v) : "f"(x)); return r;
}
__device__ __forceinline__ f32x2 f2_mul(f32x2 a, f32x2 b) {
    f32x2 r; asm("mul.rn.f32x2 %0, %1, %2;" : "=l"(r.v) : "l"(a.v), "l"(b.v)); return r;
}
__device__ __forceinline__ f32x2 f2_add(f32x2 a, f32x2 b) {
    f32x2 r; asm("add.rn.f32x2 %0, %1, %2;" : "=l"(r.v) : "l"(a.v), "l"(b.v)); return r;
}
__device__ __forceinline__ f32x2 f2_fma(f32x2 a, f32x2 b, f32x2 c) {
    f32x2 r; asm("fma.rn.f32x2 %0, %1, %2, %3;" : "=l"(r.v) : "l"(a.v), "l"(b.v), "l"(c.v)); return r;
}
__device__ __forceinline__ float f2_hadd(f32x2 a) {
    float x, y; asm("mov.b64 {%0, %1}, %2;" : "=f"(x), "=f"(y) : "l"(a.v)); return x + y;
}

// ---------------- elementwise / norm / convert kernels ----------------

__global__ void f2h_kernel(const float* __restrict__ in, __half* __restrict__ out, int n4) {
    int i = blockIdx.x * blockDim.x + threadIdx.x;
    if (i >= n4) return;
    float4 v = reinterpret_cast<const float4*>(in)[i];
    __half2* o = reinterpret_cast<__half2*>(out);
    o[2 * i]     = __floats2half2_rn(v.x, v.y);
    o[2 * i + 1] = __floats2half2_rn(v.z, v.w);
}

// concat Wspike|Wau|Wbeta into [D, NCAT] + bias concat
__global__ void wcat_kernel(const float* __restrict__ Ws, const float* __restrict__ Wa,
                            const float* __restrict__ Wb, const float* __restrict__ bau,
                            const float* __restrict__ bb,
                            float* __restrict__ wcat, float* __restrict__ bcat) {
    int idx = blockIdx.x * blockDim.x + threadIdx.x;
    if (idx < NCAT)
        bcat[idx] = (idx < 512) ? 0.f : (idx < 576) ? bau[idx - 512] : bb[idx - 576];
    if (idx >= D_ * NCAT) return;
    int k = idx / NCAT, j = idx % NCAT;
    float v;
    if (j < 512) v = Ws[k * 512 + j];
    else if (j < 576) v = Wa[k * 64 + (j - 512)];
    else v = Wb[k * 8 + (j - 576)];
    wcat[idx] = v;
}

__global__ void rmsnorm_kernel(const float* __restrict__ x, const float* __restrict__ w,
                               float* __restrict__ out) {
    int row = blockIdx.x;
    const float* xr = x + (size_t)row * D_;
    float ss = 0.f;
    for (int i = threadIdx.x; i < D_; i += 256) { float v = xr[i]; ss += v * v; }
    #pragma unroll
    for (int o = 16; o; o >>= 1) ss += __shfl_down_sync(0xffffffffu, ss, o);
    __shared__ float sh[8];
    int lane = threadIdx.x & 31, warp = threadIdx.x >> 5;
    if (lane == 0) sh[warp] = ss;
    __syncthreads();
    if (warp == 0) {
        ss = (lane < 8) ? sh[lane] : 0.f;
        #pragma unroll
        for (int o = 4; o; o >>= 1) ss += __shfl_down_sync(0xffffffffu, ss, o);
        if (lane == 0) sh[0] = ss;
    }
    __syncthreads();
    float inv = rsqrtf(sh[0] * (1.f / D_) + 1e-6f);
    for (int i = threadIdx.x; i < D_; i += 256)
        out[(size_t)row * D_ + i] = xr[i] * inv * w[i];
}

__global__ void rmsnorm_h_kernel(const float* __restrict__ x, const float* __restrict__ w,
                                 __half* __restrict__ out) {
    int row = blockIdx.x;
    const float* xr = x + (size_t)row * D_;
    float ss = 0.f;
    for (int i = threadIdx.x; i < D_; i += 256) { float v = xr[i]; ss += v * v; }
    #pragma unroll
    for (int o = 16; o; o >>= 1) ss += __shfl_down_sync(0xffffffffu, ss, o);
    __shared__ float sh[8];
    int lane = threadIdx.x & 31, warp = threadIdx.x >> 5;
    if (lane == 0) sh[warp] = ss;
    __syncthreads();
    if (warp == 0) {
        ss = (lane < 8) ? sh[lane] : 0.f;
        #pragma unroll
        for (int o = 4; o; o >>= 1) ss += __shfl_down_sync(0xffffffffu, ss, o);
        if (lane == 0) sh[0] = ss;
    }
    __syncthreads();
    float inv = rsqrtf(sh[0] * (1.f / D_) + 1e-6f);
    for (int i = threadIdx.x; i < D_; i += 256)
        out[(size_t)row * D_ + i] = __float2half(xr[i] * inv * w[i]);
}

__global__ void conv_silu_kernel(const float* __restrict__ hin, const float* __restrict__ w,
                                 const float* __restrict__ b, float* __restrict__ out,
                                 __half* __restrict__ outh) {
    int idx = blockIdx.x * blockDim.x + threadIdx.x;
    if (idx >= BT * D_) return;
    int d = idx % D_;
    int bt = idx / D_;
    int t = bt % T_;
    float acc = b[d];
    #pragma unroll
    for (int j = 0; j < 4; j++) {
        int tt = t - 3 + j;
        if (tt >= 0) acc += hin[(size_t)(bt - 3 + j) * D_ + d] * w[d * 4 + j];
    }
    float o = acc / (1.f + __expf(-acc));
    out[idx] = o;
    outh[idx] = __float2half(o);
}

__global__ void l2norm2_kernel(float* __restrict__ pq, float* __restrict__ pk) {
    float* p = blockIdx.y ? pk : pq;
    size_t base = (size_t)blockIdx.x * 64;
    float v = p[base + threadIdx.x];
    float ss = v * v;
    #pragma unroll
    for (int o = 16; o; o >>= 1) ss += __shfl_down_sync(0xffffffffu, ss, o);
    __shared__ float sh[2];
    if ((threadIdx.x & 31) == 0) sh[threadIdx.x >> 5] = ss;
    __syncthreads();
    float tot = sh[0] + sh[1];
    p[base + threadIdx.x] = v / (sqrtf(tot) + 1e-6f);
}

__global__ void headnorm_h_kernel(const float* __restrict__ p, const float* __restrict__ w,
                                  __half* __restrict__ out) {
    int h = blockIdx.x % H_;
    size_t base = (size_t)blockIdx.x * 64;
    float v = p[base + threadIdx.x];
    float ss = v * v;
    #pragma unroll
    for (int o = 16; o; o >>= 1) ss += __shfl_down_sync(0xffffffffu, ss, o);
    __shared__ float sh[2];
    if ((threadIdx.x & 31) == 0) sh[threadIdx.x >> 5] = ss;
    __syncthreads();
    float mean = (sh[0] + sh[1]) * (1.f / 64.f);
    out[base + threadIdx.x] = __float2half(v * rsqrtf(mean + 1e-6f) * w[h * 64 + threadIdx.x]);
}

// ---------------- fp32 SIMT GEMM ----------------

enum { EP_NONE = 0, EP_BIAS = 1, EP_BIAS_SILU = 2, EP_BIAS_SIGMOID = 3,
       EP_RESID_GATE = 4, EP_RESID_ADD = 5, EP_CAT = 6 };

__global__ void __launch_bounds__(256)
sgemm_kernel(const float* __restrict__ A, const float* __restrict__ Bm,
             const float* __restrict__ bias, const float* __restrict__ resid,
             const float* __restrict__ gate, float* __restrict__ C,
             float* __restrict__ outAu, float* __restrict__ outBeta,
             int M, int N, int K, int mode) {
    __shared__ float As[16][68];
    __shared__ float Bs[16][64];
    int tid = threadIdx.x;
    int tx = tid & 15, ty = tid >> 4;
    int row0 = blockIdx.y * 64;
    int col0 = blockIdx.x * 64;

    int aRow = tid >> 2, aCol = (tid & 3) * 4;
    int bRow = tid >> 4, bCol = (tid & 15) * 4;
    const bool fullN = (col0 + 64 <= N);

    float acc[4][4];
    #pragma unroll
    for (int i = 0; i < 4; i++)
        #pragma unroll
        for (int j = 0; j < 4; j++) acc[i][j] = 0.f;

    for (int k0 = 0; k0 < K; k0 += 16) {
        float4 av = *reinterpret_cast<const float4*>(&A[(size_t)(row0 + aRow) * K + k0 + aCol]);
        As[aCol + 0][aRow] = av.x; As[aCol + 1][aRow] = av.y;
        As[aCol + 2][aRow] = av.z; As[aCol + 3][aRow] = av.w;
        if (fullN) {
            *reinterpret_cast<float4*>(&Bs[bRow][bCol]) =
                *reinterpret_cast<const float4*>(&Bm[(size_t)(k0 + bRow) * N + col0 + bCol]);
        } else {
            #pragma unroll
            for (int u = 0; u < 4; u++) {
                int c = col0 + bCol + u;
                Bs[bRow][bCol + u] = (c < N) ? Bm[(size_t)(k0 + bRow) * N + c] : 0.f;
            }
        }
        __syncthreads();
        #pragma unroll
        for (int kk = 0; kk < 16; kk++) {
            float a[4], b[4];
            *reinterpret_cast<float4*>(a) = *reinterpret_cast<const float4*>(&As[kk][ty * 4]);
            *reinterpret_cast<float4*>(b) = *reinterpret_cast<const float4*>(&Bs[kk][tx * 4]);
            #pragma unroll
            for (int i = 0; i < 4; i++)
                #pragma unroll
                for (int j = 0; j < 4; j++) acc[i][j] = fmaf(a[i], b[j], acc[i][j]);
        }
        __syncthreads();
    }

    #pragma unroll
    for (int i = 0; i < 4; i++) {
        int r = row0 + ty * 4 + i;
        #pragma unroll
        for (int j = 0; j < 4; j++) {
            int c = col0 + tx * 4 + j;
            if (c >= N) continue;
            float a = acc[i][j];
            if (mode == EP_CAT) {
                float t = a + bias[c];
                if (c < 512) C[(size_t)r * 512 + c] = t;              // drive
                else if (c < 576) outAu[(size_t)r * 64 + (c - 512)] = t / (1.f + __expf(-t));
                else outBeta[(size_t)r * 8 + (c - 576)] = t;          // beta base
                continue;
            }
            float o;
            if (mode == EP_NONE) o = a;
            else if (mode == EP_BIAS) o = a + bias[c];
            else if (mode == EP_BIAS_SILU) { float t = a + bias[c]; o = t / (1.f + __expf(-t)); }
            else if (mode == EP_BIAS_SIGMOID) { float t = a + bias[c]; o = 1.f / (1.f + __expf(-t)); }
            else if (mode == EP_RESID_GATE) o = resid[(size_t)r * N + c] + a * gate[(size_t)r * N + c];
            else o = resid[(size_t)r * N + c] + a;
            C[(size_t)r * N + c] = o;
        }
    }
}

// ---------------- fp16 GEMM: m16n16k16 HMMA, cp.async double-buffered ----------------

#define HLDA 40
#define HLDB 136

__device__ __forceinline__ void hgemm_core(
    const __half* __restrict__ A, const __half* __restrict__ Bm,
    const float* __restrict__ resid, const float* __restrict__ gate,
    float* __restrict__ C, int N, int K, int mode, int row0, int col0,
    __half* sA, __half* sB)
{
    int tid = threadIdx.x;
    int warp = tid >> 5, warpM = warp & 3, warpN = warp >> 2;

    uint32_t sAu = (uint32_t)__cvta_generic_to_shared(sA);
    uint32_t sBu = (uint32_t)__cvta_generic_to_shared(sB);

    wmma::fragment<wmma::accumulator, 16, 16, 16, float> acc[2][4];
    #pragma unroll
    for (int i = 0; i < 2; i++)
        #pragma unroll
        for (int j = 0; j < 4; j++) wmma::fill_fragment(acc[i][j], 0.f);

    auto issue = [&](int stage, int k0) {
        uint32_t oA = (uint32_t)(stage * 128 * HLDA * 2);
        uint32_t oB = (uint32_t)(stage * 32 * HLDB * 2);
        #pragma unroll
        for (int i = 0; i < 2; i++) {
            int c = tid + (i << 8);
            int arr = c >> 2, acc_ = (c & 3) << 3;
            cp_async16(sAu + oA + (uint32_t)(arr * HLDA + acc_) * 2u,
                       A + (size_t)(row0 + arr) * K + k0 + acc_);
            int brr = c >> 4, bcc = (c & 15) << 3;
            cp_async16(sBu + oB + (uint32_t)(brr * HLDB + bcc) * 2u,
                       Bm + (size_t)(k0 + brr) * N + col0 + bcc);
        }
        cp_commit();
    };

    int nk = K >> 5;
    issue(0, 0);
    for (int ks = 0; ks < nk; ks++) {
        int buf = ks & 1;
        if (ks + 1 < nk) { issue(buf ^ 1, (ks + 1) << 5); cp_wait1(); }
        else cp_wait0();
        __syncthreads();
        __half* cA = sA + buf * 128 * HLDA;
        __half* cB = sB + buf * 32 * HLDB;
        #pragma unroll
        for (int kk = 0; kk < 32; kk += 16) {
            wmma::fragment<wmma::matrix_a, 16, 16, 16, __half, wmma::row_major> af[2];
            wmma::fragment<wmma::matrix_b, 16, 16, 16, __half, wmma::row_major> bf[4];
            #pragma unroll
            for (int i = 0; i < 2; i++)
                wmma::load_matrix_sync(af[i], &cA[(warpM * 32 + i * 16) * HLDA + kk], HLDA);
            #pragma unroll
            for (int j = 0; j < 4; j++)
                wmma::load_matrix_sync(bf[j], &cB[kk * HLDB + warpN * 64 + j * 16], HLDB);
            #pragma unroll
            for (int i = 0; i < 2; i++)
                #pragma unroll
                for (int j = 0; j < 4; j++)
                    wmma::mma_sync(acc[i][j], af[i], bf[j], acc[i][j]);
        }
        __syncthreads();
    }

    #pragma unroll
    for (int i = 0; i < 2; i++) {
        #pragma unroll
        for (int j = 0; j < 4; j++) {
            int r = row0 + warpM * 32 + i * 16;
            int c = col0 + warpN * 64 + j * 16;
            if (mode == EP_RESID_ADD) {
                wmma::fragment<wmma::accumulator, 16, 16, 16, float> rf;
                wmma::load_matrix_sync(rf, &resid[(size_t)r * N + c], N, wmma::mem_row_major);
                #pragma unroll
                for (int e = 0; e < rf.num_elements; e++) acc[i][j].x[e] += rf.x[e];
            } else if (mode == EP_RESID_GATE) {
                wmma::fragment<wmma::accumulator, 16, 16, 16, float> rf, gf;
                wmma::load_matrix_sync(rf, &resid[(size_t)r * N + c], N, wmma::mem_row_major);
                wmma::load_matrix_sync(gf, &gate[(size_t)r * N + c], N, wmma::mem_row_major);
                #pragma unroll
                for (int e = 0; e < rf.num_elements; e++)
                    acc[i][j].x[e] = rf.x[e] + acc[i][j].x[e] * gf.x[e];
            }
            wmma::store_matrix_sync(&C[(size_t)r * N + c], acc[i][j], N, wmma::mem_row_major);
        }
    }
}

__global__ void __launch_bounds__(256)
hgemm_kernel(const __half* __restrict__ A, const __half* __restrict__ Bm,
             const float* __restrict__ resid, const float* __restrict__ gate,
             float* __restrict__ C, int N, int K, int mode) {
    __shared__ __half sA[2 * 128 * HLDA];
    __shared__ __half sB[2 * 32 * HLDB];
    hgemm_core(A, Bm, resid, gate, C, N, K, mode, blockIdx.y * 128, blockIdx.x * 128, sA, sB);
}

__global__ void __launch_bounds__(256)
hqkv_kernel(const __half* __restrict__ A,
            const __half* __restrict__ Wq, const __half* __restrict__ Wk,
            const __half* __restrict__ Wv,
            float* __restrict__ Cq, float* __restrict__ Ck, float* __restrict__ Cv,
            int N, int K) {
    __shared__ __half sA[2 * 128 * HLDA];
    __shared__ __half sB[2 * 32 * HLDB];
    const __half* Bm = (blockIdx.z == 0) ? Wq : (blockIdx.z == 1) ? Wk : Wv;
    float* C = (blockIdx.z == 0) ? Cq : (blockIdx.z == 1) ? Ck : Cv;
    hgemm_core(A, Bm, nullptr, nullptr, C, N, K, EP_NONE, blockIdx.y * 128, blockIdx.x * 128, sA, sB);
}

// fp16 dual GEMM with direct fp16 output
#define HLDBD 72

__global__ void __launch_bounds__(256)
hdual_kernel(const __half* __restrict__ A, const __half* __restrict__ B1,
             const __half* __restrict__ B3, __half* __restrict__ C, int N, int K) {
    __shared__ __half sA[2 * 128 * HLDA];
    __shared__ __half sB1[2 * 32 * HLDBD];
    __shared__ __half sB3[2 * 32 * HLDBD];
    int tid = threadIdx.x;
    int lane = tid & 31;
    int warp = tid >> 5, warpM = warp & 3, warpN = warp >> 2;
    int row0 = blockIdx.y * 128;
    int col0 = blockIdx.x * 64;

    uint32_t sAu = (uint32_t)__cvta_generic_to_shared(sA);
    uint32_t sB1u = (uint32_t)__cvta_generic_to_shared(sB1);
    uint32_t sB3u = (uint32_t)__cvta_generic_to_shared(sB3);

    wmma::fragment<wmma::accumulator, 16, 16, 16, float> acc1[2][2], acc3[2][2];
    #pragma unroll
    for (int i = 0; i < 2; i++)
        #pragma unroll
        for (int j = 0; j < 2; j++) { wmma::fill_fragment(acc1[i][j], 0.f); wmma::fill_fragment(acc3[i][j], 0.f); }

    auto issue = [&](int stage, int k0) {
        uint32_t oA = (uint32_t)(stage * 128 * HLDA * 2);
        uint32_t oB = (uint32_t)(stage * 32 * HLDBD * 2);
        #pragma unroll
        for (int i = 0; i < 2; i++) {
            int c = tid + (i << 8);
            int arr = c >> 2, acc_ = (c & 3) << 3;
            cp_async16(sAu + oA + (uint32_t)(arr * HLDA + acc_) * 2u,
                       A + (size_t)(row0 + arr) * K + k0 + acc_);
        }
        int brr = tid >> 3, bcc = (tid & 7) << 3;
        cp_async16(sB1u + oB + (uint32_t)(brr * HLDBD + bcc) * 2u,
                   B1 + (size_t)(k0 + brr) * N + col0 + bcc);
        cp_async16(sB3u + oB + (uint32_t)(brr * HLDBD + bcc) * 2u,
                   B3 + (size_t)(k0 + brr) * N + col0 + bcc);
        cp_commit();
    };

    int nk = K >> 5;
    issue(0, 0);
    for (int ks = 0; ks < nk; ks++) {
        int buf = ks & 1;
        if (ks + 1 < nk) { issue(buf ^ 1, (ks + 1) << 5); cp_wait1(); }
        else cp_wait0();
        __syncthreads();
        __half* cA = sA + buf * 128 * HLDA;
        __half* cB1 = sB1 + buf * 32 * HLDBD;
        __half* cB3 = sB3 + buf * 32 * HLDBD;
        #pragma unroll
        for (int kk = 0; kk < 32; kk += 16) {
            wmma::fragment<wmma::matrix_a, 16, 16, 16, __half, wmma::row_major> af[2];
            wmma::fragment<wmma::matrix_b, 16, 16, 16, __half, wmma::row_major> b1f[2], b3f[2];
            #pragma unroll
            for (int i = 0; i < 2; i++)
                wmma::load_matrix_sync(af[i], &cA[(warpM * 32 + i * 16) * HLDA + kk], HLDA);
            #pragma unroll
            for (int j = 0; j < 2; j++) {
                wmma::load_matrix_sync(b1f[j], &cB1[kk * HLDBD + warpN * 32 + j * 16], HLDBD);
                wmma::load_matrix_sync(b3f[j], &cB3[kk * HLDBD + warpN * 32 + j * 16], HLDBD);
            }
            #pragma unroll
            for (int i = 0; i < 2; i++)
                #pragma unroll
                for (int j = 0; j < 2; j++) {
                    wmma::mma_sync(acc1[i][j], af[i], b1f[j], acc1[i][j]);
                    wmma::mma_sync(acc3[i][j], af[i], b3f[j], acc3[i][j]);
                }
        }
        __syncthreads();
    }
    float* stage = reinterpret_cast<float*>(sA) + warp * 256;
    #pragma unroll
    for (int i = 0; i < 2; i++)
        #pragma unroll
        for (int j = 0; j < 2; j++) {
            #pragma unroll
            for (int e = 0; e < acc1[i][j].num_elements; e++) {
                float t = acc1[i][j].x[e];
                acc1[i][j].x[e] = (t / (1.f + __expf(-t))) * acc3[i][j].x[e];
            }
            wmma::store_matrix_sync(stage, acc1[i][j], 16, wmma::mem_row_major);
            __syncwarp();
            int r = lane >> 1, c0 = (lane & 1) << 3;
            int R = row0 + warpM * 32 + i * 16 + r;
            int Cc = col0 + warpN * 32 + j * 16 + c0;
            __half2* dst = reinterpret_cast<__half2*>(C + (size_t)R * N + Cc);
            #pragma unroll
            for (int u = 0; u < 4; u++)
                dst[u] = __floats2half2_rn(stage[r * 16 + c0 + 2 * u], stage[r * 16 + c0 + 2 * u + 1]);
            __syncwarp();
        }
}

// ---------------- scan v4: smem-based spike-sum (no shuffle chain on the spine) ----------------
__global__ void __launch_bounds__(64)
scan2_kernel(const float* __restrict__ q, const float* __restrict__ k,
             const float* __restrict__ v, const float* __restrict__ drive,
             const float* __restrict__ ab, const float* __restrict__ betab,
             const float* __restrict__ asp, const float* __restrict__ bsp,
             float* __restrict__ yout) {
    int bh = blockIdx.x;
    int b = bh / H_, h = bh % H_;
    int tid = threadIdx.x;

    __shared__ __align__(8) float sk[2][64], sq_[2][64], sal[2][64], sspb[2][64];

    f32x2 s2[32];
    #pragma unroll
    for (int i = 0; i < 32; i++) s2[i] = f2_zero();

    float m = 0.f;
    float aspv = asp[h * 64 + tid];
    float bspv = bsp[h * 64 + tid];

    size_t rowbase = (size_t)(b * T_) * HD + (size_t)h * 64;
    const float* bb = betab + (size_t)(b * T_) * H_ + h;

    size_t qo = rowbase;
    float dv_ = drive[qo + tid], abv = ab[qo + tid];
    float kv = k[qo + tid], qv = q[qo + tid], vv = v[qo + tid];
    float bbv = bb[0];

    for (int t = 0; t < T_; t++) {
        int pb = t & 1;
        size_t qn = qo + HD;
        m = 0.9f * m + dv_;
        float spk = (m > 0.5f) ? 1.f : 0.f;
        m -= 0.5f * spk;
        float al = 1.f / (1.f + __expf(-(abv + aspv * spk)));
        sk[pb][tid] = kv;
        sq_[pb][tid] = qv;
        sal[pb][tid] = al;
        sspb[pb][tid] = spk * bspv;     // replaces 5-deep shuffle chain
        float vcur = vv, bbcur = bbv;
        if (t + 1 < T_) {
            dv_ = drive[qn + tid]; abv = ab[qn + tid];
            kv = k[qn + tid]; qv = q[qn + tid]; vv = v[qn + tid];
            bbv = bb[(size_t)(t + 1) * H_];
        }
        int cnt = __syncthreads_count(spk > 0.5f);
        const unsigned long long* k2 = (const unsigned long long*)sk[pb];
        const unsigned long long* q2 = (const unsigned long long*)sq_[pb];
        const unsigned long long* a2 = (const unsigned long long*)sal[pb];
        const unsigned long long* sb2 = (const unsigned long long*)sspb[pb];
        float out;
        if (cnt > 0) {
            f32x2 p0 = f2_zero(), p1 = f2_zero(), p2 = f2_zero(), p3 = f2_zero();
            f32x2 w0 = f2_zero(), w1 = f2_zero(), w2 = f2_zero(), w3 = f2_zero();
            f32x2 kr[32];
            #pragma unroll
            for (int i = 0; i < 32; i += 4) {
                kr[i].v = k2[i]; kr[i+1].v = k2[i+1]; kr[i+2].v = k2[i+2]; kr[i+3].v = k2[i+3];
                f32x2 a0, a1, a3, a4;
                a0.v = a2[i]; a1.v = a2[i+1]; a3.v = a2[i+2]; a4.v = a2[i+3];
                s2[i]   = f2_mul(s2[i],   a0);
                s2[i+1] = f2_mul(s2[i+1], a1);
                s2[i+2] = f2_mul(s2[i+2], a3);
                s2[i+3] = f2_mul(s2[i+3], a4);
                p0 = f2_fma(kr[i],   s2[i],   p0);
                p1 = f2_fma(kr[i+1], s2[i+1], p1);
                p2 = f2_fma(kr[i+2], s2[i+2], p2);
                p3 = f2_fma(kr[i+3], s2[i+3], p3);
                // redundant per-thread spike-weight sum (independent; dual-issues with FMA chain)
                f32x2 b0, b1, b3x, b4;
                b0.v = sb2[i]; b1.v = sb2[i+1]; b3x.v = sb2[i+2]; b4.v = sb2[i+3];
                w0 = f2_add(w0, b0);
                w1 = f2_add(w1, b1);
                w2 = f2_add(w2, b3x);
                w3 = f2_add(w3, b4);
            }
            float pred = f2_hadd(f2_add(f2_add(p0, p1), f2_add(p2, p3)));
            float wsumv = f2_hadd(f2_add(f2_add(w0, w1), f2_add(w2, w3)));
            float braw = bbcur + wsumv;
            float beta = 1.f / (1.f + __expf(-braw));
            float bd = beta * (vcur - pred);
            f32x2 bd2 = f2_bcast(bd);
            f32x2 o0 = f2_zero(), o1 = f2_zero(), o2 = f2_zero(), o3 = f2_zero();
            #pragma unroll
            for (int i = 0; i < 32; i += 4) {
                f32x2 q0, q1, q3, q4;
                q0.v = q2[i]; q1.v = q2[i+1]; q3.v = q2[i+2]; q4.v = q2[i+3];
                s2[i]   = f2_fma(kr[i],   bd2, s2[i]);
                s2[i+1] = f2_fma(kr[i+1], bd2, s2[i+1]);
                s2[i+2] = f2_fma(kr[i+2], bd2, s2[i+2]);
                s2[i+3] = f2_fma(kr[i+3], bd2, s2[i+3]);
                o0 = f2_fma(q0, s2[i],   o0);
                o1 = f2_fma(q1, s2[i+1], o1);
                o2 = f2_fma(q3, s2[i+2], o2);
                o3 = f2_fma(q4, s2[i+3], o3);
            }
            out = f2_hadd(f2_add(f2_add(o0, o1), f2_add(o2, o3)));
        } else {
            f32x2 o0 = f2_zero(), o1 = f2_zero(), o2 = f2_zero(), o3 = f2_zero();
            #pragma unroll
            for (int i = 0; i < 32; i += 4) {
                f32x2 q0, q1, q3, q4;
                q0.v = q2[i]; q1.v = q2[i+1]; q3.v = q2[i+2]; q4.v = q2[i+3];
                o0 = f2_fma(q0, s2[i],   o0);
                o1 = f2_fma(q1, s2[i+1], o1);
                o2 = f2_fma(q3, s2[i+2], o2);
                o3 = f2_fma(q4, s2[i+3], o3);
            }
            out = f2_hadd(f2_add(f2_add(o0, o1), f2_add(o2, o3)));
        }
        yout[qo + tid] = out;
        qo = qn;
    }
}

// ---------------- host launch ----------------

template <typename Tsym>
static void* symaddr_v(const Tsym& s) {
    void* p = nullptr;
    cudaGetSymbolAddress(&p, s);
    return p;
}

static void gemm_s(cudaStream_t st, const float* A, const float* Bm, const float* bias,
                   const float* resid, const float* gate, float* C,
                   int M, int N, int K, int mode,
                   float* outAu = nullptr, float* outBeta = nullptr) {
    dim3 grid((N + 63) / 64, M / 64);
    sgemm_kernel<<<grid, 256, 0, st>>>(A, Bm, bias, resid, gate, C, outAu, outBeta, M, N, K, mode);
}

static void hgemm(const __half* A, const __half* Bm, const float* resid,
                  const float* gate, float* C, int M, int N, int K, int mode) {
    dim3 grid(N / 128, M / 128);
    hgemm_kernel<<<grid, 256>>>(A, Bm, resid, gate, C, N, K, mode);
}

static void f2h_s(cudaStream_t st, const float* in, __half* out, int n) {
    f2h_kernel<<<(n / 4 + 255) / 256, 256, 0, st>>>(in, out, n / 4);
}

extern "C" void kernel_launch(void* const* d_in, const int* in_sizes, int n_in,
                              void* d_out, int out_size) {
    const float* x          = (const float*)d_in[0];
    const float* norm_in_w  = (const float*)d_in[1];
    const float* conv_w     = (const float*)d_in[2];
    const float* conv_b     = (const float*)d_in[3];
    const float* Wq         = (const float*)d_in[4];
    const float* Wk         = (const float*)d_in[5];
    const float* Wv         = (const float*)d_in[6];
    const float* Wo         = (const float*)d_in[7];
    const float* Wspike     = (const float*)d_in[8];
    const float* Wau        = (const float*)d_in[9];
    const float* bau        = (const float*)d_in[10];
    const float* Wad        = (const float*)d_in[11];
    const float* bad        = (const float*)d_in[12];
    const float* alpha_sp   = (const float*)d_in[13];
    const float* Wbeta      = (const float*)d_in[14];
    const float* bbeta      = (const float*)d_in[15];
    const float* beta_sp    = (const float*)d_in[16];
    const float* head_nw    = (const float*)d_in[17];
    const float* Wu1        = (const float*)d_in[18];
    const float* bu1        = (const float*)d_in[19];
    const float* Wu2        = (const float*)d_in[20];
    const float* bu2        = (const float*)d_in[21];
    const float* ff_norm_w  = (const float*)d_in[22];
    const float* Wff1       = (const float*)d_in[23];
    const float* Wff3       = (const float*)d_in[24];
    const float* Wff2       = (const float*)d_in[25];
    float* out = (float*)d_out;

    float* p_tmp    = (float*)symaddr_v(g_tmp);
    float* p_h      = (float*)symaddr_v(g_h);
    float* p_q      = (float*)symaddr_v(g_q);
    float* p_k      = (float*)symaddr_v(g_k);
    float* p_v      = (float*)symaddr_v(g_v);
    float* p_drive  = (float*)symaddr_v(g_drive);
    float* p_ab     = (float*)symaddr_v(g_ab);
    float* p_au     = (float*)symaddr_v(g_au);
    float* p_beta   = (float*)symaddr_v(g_beta);
    float* p_yattn  = (float*)symaddr_v(g_yattn);
    float* p_u1     = (float*)symaddr_v(g_u1);
    float* p_gate   = (float*)symaddr_v(g_gate);
    float* p_y2     = (float*)symaddr_v(g_y2);
    float* p_wcat   = (float*)symaddr_v(g_wcat);
    float* p_bcat   = (float*)symaddr_v(g_bcat);
    __half* p_hh    = (__half*)symaddr_v(g_hh);
    __half* p_yattnh= (__half*)symaddr_v(g_yattnh);
    __half* p_zh    = (__half*)symaddr_v(g_zh);
    __half* p_ffah  = (__half*)symaddr_v(g_ffah);
    __half* p_wqh   = (__half*)symaddr_v(g_wqh);
    __half* p_wkh   = (__half*)symaddr_v(g_wkh);
    __half* p_wvh   = (__half*)symaddr_v(g_wvh);
    __half* p_woh   = (__half*)symaddr_v(g_woh);
    __half* p_wff1h = (__half*)symaddr_v(g_wff1h);
    __half* p_wff3h = (__half*)symaddr_v(g_wff3h);
    __half* p_wff2h = (__half*)symaddr_v(g_wff2h);

    // one-time host-side resources (no device memory)
    static cudaStream_t s1 = nullptr, s2 = nullptr, s3 = nullptr;
    static cudaEvent_t ev0, ev1, evh, ev2, ev3, ev4;
    if (s1 == nullptr) {
        cudaStreamCreateWithFlags(&s1, cudaStreamNonBlocking);
        cudaStreamCreateWithFlags(&s2, cudaStreamNonBlocking);
        cudaStreamCreateWithFlags(&s3, cudaStreamNonBlocking);
        cudaEventCreateWithFlags(&ev0, cudaEventDisableTiming);
        cudaEventCreateWithFlags(&ev1, cudaEventDisableTiming);
        cudaEventCreateWithFlags(&evh, cudaEventDisableTiming);
        cudaEventCreateWithFlags(&ev2, cudaEventDisableTiming);
        cudaEventCreateWithFlags(&ev3, cudaEventDisableTiming);
        cudaEventCreateWithFlags(&ev4, cudaEventDisableTiming);
    }

    // fork: weight prep on s1, concurrent with rmsnorm+conv on main
    cudaEventRecord(ev0, 0);
    cudaStreamWaitEvent(s1, ev0, 0);
    f2h_s(s1, Wq, p_wqh, D_ * HD);
    f2h_s(s1, Wk, p_wkh, D_ * HD);
    f2h_s(s1, Wv, p_wvh, D_ * HD);
    f2h_s(s1, Wo, p_woh, HD * D_);
    f2h_s(s1, Wff1, p_wff1h, D_ * DFF);
    f2h_s(s1, Wff3, p_wff3h, D_ * DFF);
    f2h_s(s1, Wff2, p_wff2h, DFF * D_);
    wcat_kernel<<<(D_ * NCAT + 255) / 256, 256, 0, s1>>>(Wspike, Wau, Wbeta, bau, bbeta, p_wcat, p_bcat);
    cudaEventRecord(ev1, s1);

    // main: input norm + conv
    rmsnorm_kernel<<<BT, 256>>>(x, norm_in_w, p_tmp);
    conv_silu_kernel<<<(BT * D_ + 255) / 256, 256>>>(p_tmp, conv_w, conv_b, p_h, p_hh);
    cudaEventRecord(evh, 0);
    cudaStreamWaitEvent(0, ev1, 0);   // main needs fp16 weights for QKV

    // fork: drive/alpha path (fp32, FMA pipe) on s3 — overlaps QKV (tensor pipe)
    cudaStreamWaitEvent(s3, evh, 0);
    cudaStreamWaitEvent(s3, ev1, 0);
    gemm_s(s3, p_h, p_wcat, p_bcat, nullptr, nullptr, p_drive, BT, NCAT, D_, EP_CAT, p_au, p_beta);
    gemm_s(s3, p_au, Wad, bad, nullptr, nullptr, p_ab, BT, HD, R_, EP_BIAS);
    cudaEventRecord(ev4, s3);

    // main: q/k/v projections (fp16 HMMA) + l2norm
    {
        dim3 grid(HD / 128, BT / 128, 3);
        hqkv_kernel<<<grid, 256>>>(p_hh, p_wqh, p_wkh, p_wvh, p_q, p_k, p_v, HD, D_);
    }
    {
        dim3 grid(BT * H_, 2);
        l2norm2_kernel<<<grid, 64>>>(p_q, p_k);
    }
    cudaEventRecord(ev2, 0);

    // fork: gate path on s2, scheduled into the scan's idle window
    cudaStreamWaitEvent(s2, ev2, 0);
    gemm_s(s2, x, Wu1, bu1, nullptr, nullptr, p_u1, BT, R_, D_, EP_BIAS_SILU);
    gemm_s(s2, p_u1, Wu2, bu2, nullptr, nullptr, p_gate, BT, D_, R_, EP_BIAS_SIGMOID);
    cudaEventRecord(ev3, s2);

    // main: join drive path, then scan (gate path fills the idle SMs)
    cudaStreamWaitEvent(0, ev4, 0);
    scan2_kernel<<<B_ * H_, 64>>>(p_q, p_k, p_v, p_drive, p_ab, p_beta,
                                  alpha_sp, beta_sp, p_yattn);
    headnorm_h_kernel<<<BT * H_, 64>>>(p_yattn, head_nw, p_yattnh);
    cudaStreamWaitEvent(0, ev3, 0);   // join: need gate

    // y2 = x + (yattn@Wo) * gate
    hgemm(p_yattnh, p_woh, x, p_gate, p_y2, BT, D_, HD, EP_RESID_GATE);
    // FFN
    rmsnorm_h_kernel<<<BT, 256>>>(p_y2, ff_norm_w, p_zh);
    {
        dim3 grid(DFF / 64, BT / 128);
        hdual_kernel<<<grid, 256>>>(p_zh, p_wff1h, p_wff3h, p_ffah, DFF, D_);
    }
    hgemm(p_ffah, p_wff2h, p_y2, nullptr, out, BT, D_, DFF, EP_RESID_ADD);
}